// round 6
// baseline (speedup 1.0000x reference)
#include <cuda_runtime.h>
#include <math_constants.h>

#define IMG    256
#define DET    362          // int(256*sqrt(2)+0.5)
#define A_FULL 177          // (45-1)*4 + 1
#define N_ACQ  45
#define NB     2
#define NCHUNK 4
#define CHSZ   ((DET + NCHUNK - 1) / NCHUNK)   // 91

// Padded image geometry: 2-cell zero border (coords can reach index -2..257)
#define PW     264          // padded row stride in ELEMENTS (float2)
#define PH     260          // 2 top + 256 + 2 bottom
#define POFF   (2 * PW + 2) // offset of pixel (0,0)

// bp chunking
#define NCHBP  4
#define ABP    45           // ceil(177/4)

// Scratch (allocation-free)
__device__ float  g_part[NCHUNK * NB * A_FULL * DET];  // radon partials
__device__ float2 g_sf2 [NB * A_FULL * DET];           // filtered sinogram, pair-packed
__device__ float2 g_imP2 [NB * PH * PW];               // padded image, pair-packed
__device__ float2 g_imTP2[NB * PH * PW];               // padded transposed image, pair-packed
__device__ float  g_bp  [NCHBP * NB * IMG * IMG];      // backprojection partials

// ---------------------------------------------------------------------------
// Kernel 0: build zero-padded pair-packed image + transposed image.
// P2[r][c] = (I[r][c], I[r][c+1]);  T2[r][c] = (I[c][r], I[c+1][r]).
// ---------------------------------------------------------------------------
__global__ void prep_kernel(const float* __restrict__ img)
{
    const int i = blockIdx.x * blockDim.x + threadIdx.x;
    if (i >= NB * PH * PW) return;
    const int b   = i / (PH * PW);
    const int rem = i - b * (PH * PW);
    const int r   = rem / PW - 2;     // image row  in [-2, PH-3]
    const int c   = rem - (r + 2) * PW - 2;  // image col in [-2, PW-3]
    const float* im = img + b * IMG * IMG;

    const bool rv = ((unsigned)r < IMG);
    const bool cv0 = ((unsigned)c < IMG);
    const bool cv1 = ((unsigned)(c + 1) < IMG);

    float2 v, vt;
    v.x  = (rv  && cv0) ? __ldg(im + r * IMG + c)       : 0.f;
    v.y  = (rv  && cv1) ? __ldg(im + r * IMG + c + 1)   : 0.f;
    vt.x = (cv0 && rv ) ? __ldg(im + c * IMG + r)       : 0.f;
    vt.y = (cv1 && rv ) ? __ldg(im + (c + 1) * IMG + r) : 0.f;
    g_imP2 [i] = v;
    g_imTP2[i] = vt;
}

// ---------------------------------------------------------------------------
// Kernel 1: Radon transform, chunked over S; 2x LDG.64 per bilinear sample.
// grid = (A_FULL, NB, NCHUNK), block = 384 (one thread per detector bin t).
// ---------------------------------------------------------------------------
__global__ void radon_kernel(const float* __restrict__ thetas_deg)
{
    const int a  = blockIdx.x;
    const int b  = blockIdx.y;
    const int ch = blockIdx.z;
    const int t  = threadIdx.x;
    if (t >= DET) return;

    const float th = thetas_deg[a] * (float)(CUDART_PI / 180.0);
    const float c  = cosf(th);
    const float s  = sinf(th);

    const float T  = (float)t - (float)(DET - 1) * 0.5f;
    const float bx = T * c + 127.5f;
    const float by = T * s + 127.5f;

    const bool swp = (s > fabsf(c));
    float q0, r0, dq, dr;
    const float2* imc;
    if (swp) { q0 = by; r0 = bx; dq =  c; dr = -s; imc = g_imTP2 + b * PH * PW + POFF; }
    else     { q0 = bx; r0 = by; dq = -s; dr =  c; imc = g_imP2  + b * PH * PW + POFF; }

    // Valid S interval: q0+S*dq in (-1,256) and r0+S*dr in (-1,256)
    float Slo = -1e9f, Shi = 1e9f;
    if (dq > 1e-6f)       { Slo = fmaxf(Slo, (-1.f - q0) / dq); Shi = fminf(Shi, (256.f - q0) / dq); }
    else if (dq < -1e-6f) { Slo = fmaxf(Slo, (256.f - q0) / dq); Shi = fminf(Shi, (-1.f - q0) / dq); }
    else if (q0 <= -1.f || q0 >= 256.f) Shi = -2e9f;
    if (dr > 1e-6f)       { Slo = fmaxf(Slo, (-1.f - r0) / dr); Shi = fminf(Shi, (256.f - r0) / dr); }
    else if (dr < -1e-6f) { Slo = fmaxf(Slo, (256.f - r0) / dr); Shi = fminf(Shi, (-1.f - r0) / dr); }
    else if (r0 <= -1.f || r0 >= 256.f) Shi = -2e9f;

    const float HALF = (float)(DET - 1) * 0.5f;   // 180.5
    int klo = (int)floorf(Slo + HALF);            // <=1 step outside: pad absorbs it
    int khi = (int)ceilf (Shi + HALF) + 1;        // exclusive
    klo = max(klo, ch * CHSZ);
    khi = min(khi, min(DET, (ch + 1) * CHSZ));

    float acc = 0.f;
    #pragma unroll 4
    for (int k = klo; k < khi; k++) {
        const float S  = (float)k - HALF;
        const float qs = fmaf(S, dq, q0);
        const float rs = fmaf(S, dr, r0);
        const float qf = floorf(qs), rf = floorf(rs);
        const float wq = qs - qf,    wr = rs - rf;
        const int   qi = (int)qf,    ri = (int)rf;

        const float2* p = imc + ri * PW + qi;
        const float2 a0 = __ldg(p);        // (v00, v01)
        const float2 a1 = __ldg(p + PW);   // (v10, v11)

        const float top = fmaf(wq, a0.y - a0.x, a0.x);
        const float bot = fmaf(wq, a1.y - a1.x, a1.x);
        acc = fmaf(wr, bot - top, acc + top);
    }

    g_part[((ch * NB + b) * A_FULL + a) * DET + t] = acc;
}

// ---------------------------------------------------------------------------
// Kernel 2: combine partials + data-consistency + exact ramp-filter conv,
// writing the pair-packed filtered sinogram.
//   h[0]=0.5, h[m odd]=-2/(pi m)^2, h[m even>0]=0 (exactly the FFT filter)
// ---------------------------------------------------------------------------
__global__ void filter_kernel(const float* __restrict__ s_target)
{
    __shared__ float xcol[DET];
    __shared__ float wtab[DET];
    __shared__ float res [DET];

    const int a = blockIdx.x;
    const int b = blockIdx.y;
    const int d = threadIdx.x;

    for (int i = threadIdx.x; i < DET; i += blockDim.x) {
        float x = 0.f;
        #pragma unroll
        for (int ci = 0; ci < NCHUNK; ci++)
            x += g_part[((ci * NB + b) * A_FULL + a) * DET + i];
        if ((a & 3) == 0) {
            const int j = a >> 2;
            x = __ldg(s_target + (b * DET + i) * N_ACQ + j) - x;
        }
        xcol[i] = x;

        float wm;
        if (i == 0)      wm = 0.5f;
        else if (i & 1)  { const float fm = (float)i * (float)CUDART_PI; wm = -2.0f / (fm * fm); }
        else             wm = 0.f;
        wtab[i] = wm;
    }
    __syncthreads();

    if (d < DET) {
        float acc = 0.5f * xcol[d];
        const int k0 = (d & 1) ^ 1;       // opposite parity -> |d-k| odd
        #pragma unroll 4
        for (int k = k0; k < DET; k += 2) {
            const int m = abs(d - k);
            acc += wtab[m] * xcol[k];
        }
        res[d] = acc;
    }
    __syncthreads();

    if (d < DET) {
        float2 o;
        o.x = res[d];
        o.y = (d + 1 < DET) ? res[d + 1] : 0.f;
        g_sf2[(b * A_FULL + a) * DET + d] = o;
    }
}

// ---------------------------------------------------------------------------
// Kernel 3: Filtered backprojection, chunked over angles; 1x LDG.64 / sample.
// grid = (512, NCHBP), block = 256.
// ---------------------------------------------------------------------------
__global__ void bp_kernel(const float* __restrict__ thetas_deg)
{
    __shared__ float cs[ABP];
    __shared__ float sn[ABP];

    const int ch  = blockIdx.y;
    const int a0  = ch * ABP;
    const int na  = min(A_FULL - a0, ABP);

    if (threadIdx.x < na) {
        const float th = thetas_deg[a0 + threadIdx.x] * (float)(CUDART_PI / 180.0);
        cs[threadIdx.x] = cosf(th);
        sn[threadIdx.x] = sinf(th);
    }
    __syncthreads();

    const int p   = blockIdx.x * blockDim.x + threadIdx.x;   // 0 .. 131071
    const int b   = p >> 16;
    const int pix = p & 65535;
    const int y   = pix >> 8;
    const int x   = pix & 255;

    const float gx = (float)x - 127.5f;
    const float gy = (float)y - 127.5f;

    const float2* __restrict__ sfb = g_sf2 + (b * A_FULL + a0) * DET;

    float acc = 0.f;
    #pragma unroll 3
    for (int a = 0; a < na; a++) {
        const float t  = fmaf(cs[a], gx, fmaf(sn[a], gy, (float)(DET - 1) * 0.5f));
        const float t0 = floorf(t);
        const float w  = t - t0;
        const int   i  = (int)t0;           // always in [0, 360]
        const float2 v = __ldg(sfb + a * DET + i);
        acc = fmaf(w, v.y - v.x, acc + v.x);
    }
    g_bp[ch * (NB * IMG * IMG) + p] = acc;
}

// ---------------------------------------------------------------------------
// Kernel 4: reduce bp partials + scale.
// ---------------------------------------------------------------------------
__global__ void bp_reduce_kernel(float* __restrict__ out)
{
    const int p = blockIdx.x * blockDim.x + threadIdx.x;
    if (p >= NB * IMG * IMG) return;
    float acc = 0.f;
    #pragma unroll
    for (int ci = 0; ci < NCHBP; ci++)
        acc += g_bp[ci * (NB * IMG * IMG) + p];
    out[p] = acc * (float)(CUDART_PI / (2.0 * A_FULL));
}

// ---------------------------------------------------------------------------
extern "C" void kernel_launch(void* const* d_in, const int* in_sizes, int n_in,
                              void* d_out, int out_size)
{
    const float* x_source = nullptr;
    const float* s_target = nullptr;
    const float* thetas   = nullptr;
    for (int i = 0; i < n_in; i++) {
        if      (in_sizes[i] == NB * IMG * IMG)   x_source = (const float*)d_in[i];
        else if (in_sizes[i] == NB * DET * N_ACQ) s_target = (const float*)d_in[i];
        else if (in_sizes[i] == A_FULL)           thetas   = (const float*)d_in[i];
    }

    prep_kernel     <<<(NB * PH * PW + 255) / 256, 256>>>(x_source);
    radon_kernel    <<<dim3(A_FULL, NB, NCHUNK), 384>>>(thetas);
    filter_kernel   <<<dim3(A_FULL, NB), 384>>>(s_target);
    bp_kernel       <<<dim3(512, NCHBP), 256>>>(thetas);
    bp_reduce_kernel<<<512, 256>>>((float*)d_out);
}

// round 7
// speedup vs baseline: 1.0987x; 1.0987x over previous
#include <cuda_runtime.h>
#include <math_constants.h>

#define IMG    256
#define DET    362          // int(256*sqrt(2)+0.5)
#define A_FULL 177          // (45-1)*4 + 1
#define N_ACQ  45
#define NB     2

// Padded image geometry: 2-cell zero border (coords reach index -2..256)
#define PW     264          // padded row stride in float4 quads
#define PH     260
#define POFF   (2 * PW + 2)

// radon warp tiling: 8 t-bins x 4 k-samples per warp
#define TPB    256          // 8 warps -> 64 t-bins per block
#define TTILES 6            // ceil(362/64)

// bp chunking
#define NCHBP  4
#define ABP    45           // ceil(177/4)

// Scratch (allocation-free)
__device__ float  g_sino[NB * A_FULL * DET];   // radon output
__device__ float2 g_sf2 [NB * A_FULL * DET];   // filtered sinogram, pair-packed
__device__ float4 g_imQ  [NB * PH * PW];       // quad-packed padded image
__device__ float4 g_imTQ [NB * PH * PW];       // quad-packed padded transposed image
__device__ float  g_bp  [NCHBP * NB * IMG * IMG];

// ---------------------------------------------------------------------------
// Kernel 0: build quad-packed padded images.
// imQ [r][c] = (I[r][c],  I[r][c+1],  I[r+1][c],  I[r+1][c+1])
// imTQ[r][c] = (I[c][r],  I[c+1][r],  I[c][r+1],  I[c+1][r+1])
// ---------------------------------------------------------------------------
__global__ void prep_kernel(const float* __restrict__ img)
{
    const int i = blockIdx.x * blockDim.x + threadIdx.x;
    if (i >= NB * PH * PW) return;
    const int b   = i / (PH * PW);
    const int rem = i - b * (PH * PW);
    const int r   = rem / PW - 2;
    const int c   = rem - (r + 2) * PW - 2;
    const float* im = img + b * IMG * IMG;

    const bool rv0 = ((unsigned)r       < IMG);
    const bool rv1 = ((unsigned)(r + 1) < IMG);
    const bool cv0 = ((unsigned)c       < IMG);
    const bool cv1 = ((unsigned)(c + 1) < IMG);

    float4 v, vt;
    v.x  = (rv0 && cv0) ? __ldg(im + r * IMG + c)             : 0.f;
    v.y  = (rv0 && cv1) ? __ldg(im + r * IMG + c + 1)         : 0.f;
    v.z  = (rv1 && cv0) ? __ldg(im + (r + 1) * IMG + c)       : 0.f;
    v.w  = (rv1 && cv1) ? __ldg(im + (r + 1) * IMG + c + 1)   : 0.f;
    vt.x = (cv0 && rv0) ? __ldg(im + c * IMG + r)             : 0.f;
    vt.y = (cv1 && rv0) ? __ldg(im + (c + 1) * IMG + r)       : 0.f;
    vt.z = (cv0 && rv1) ? __ldg(im + c * IMG + r + 1)         : 0.f;
    vt.w = (cv1 && rv1) ? __ldg(im + (c + 1) * IMG + r + 1)   : 0.f;
    g_imQ [i] = v;
    g_imTQ[i] = vt;
}

// ---------------------------------------------------------------------------
// Kernel 1: Radon transform. grid = (A_FULL, NB, TTILES), block = 256.
// Warp = 8 t-bins x 4 k-strides; one LDG.128 per bilinear sample.
// ---------------------------------------------------------------------------
__global__ void radon_kernel(const float* __restrict__ thetas_deg)
{
    const int a    = blockIdx.x;
    const int b    = blockIdx.y;
    const int w    = threadIdx.x >> 5;
    const int lane = threadIdx.x & 31;
    const int tt   = lane & 7;
    const int kk   = lane >> 3;
    const int t    = blockIdx.z * 64 + w * 8 + tt;

    const float th = thetas_deg[a] * (float)(CUDART_PI / 180.0);
    const float c  = cosf(th);
    const float s  = sinf(th);

    const bool swp = (s > fabsf(c));
    const float4* imc = (swp ? g_imTQ : g_imQ) + b * PH * PW + POFF;

    // per-lane ray parameters (valid only for t < DET)
    float q0 = 0.f, r0 = 0.f, dq = 0.f, dr = 0.f;
    int klo = DET, khi = 0;                 // empty interval by default
    if (t < DET) {
        const float T  = (float)t - (float)(DET - 1) * 0.5f;
        const float bx = T * c + 127.5f;
        const float by = T * s + 127.5f;
        if (swp) { q0 = by; r0 = bx; dq =  c; dr = -s; }
        else     { q0 = bx; r0 = by; dq = -s; dr =  c; }

        float Slo = -1e9f, Shi = 1e9f;
        if (dq > 1e-6f)       { Slo = fmaxf(Slo, (-1.f - q0) / dq); Shi = fminf(Shi, (256.f - q0) / dq); }
        else if (dq < -1e-6f) { Slo = fmaxf(Slo, (256.f - q0) / dq); Shi = fminf(Shi, (-1.f - q0) / dq); }
        else if (q0 <= -1.f || q0 >= 256.f) Shi = -2e9f;
        if (dr > 1e-6f)       { Slo = fmaxf(Slo, (-1.f - r0) / dr); Shi = fminf(Shi, (256.f - r0) / dr); }
        else if (dr < -1e-6f) { Slo = fmaxf(Slo, (256.f - r0) / dr); Shi = fminf(Shi, (-1.f - r0) / dr); }
        else if (r0 <= -1.f || r0 >= 256.f) Shi = -2e9f;

        const float HALF = (float)(DET - 1) * 0.5f;
        klo = (int)floorf(Slo + HALF);          // pad absorbs <=1-step slack
        khi = (int)ceilf (Shi + HALF) + 1;
        klo = max(klo, 0);
        khi = min(khi, DET);
        if (khi < klo) { klo = DET; khi = 0; }
    }

    // warp-uniform k range
    const int kmin = __reduce_min_sync(0xffffffffu, klo);
    const int kmax = __reduce_max_sync(0xffffffffu, khi);

    const float HALF = (float)(DET - 1) * 0.5f;
    float acc = 0.f;
    for (int k = kmin + kk; k < kmax; k += 4) {
        if (k >= klo && k < khi) {
            const float S  = (float)k - HALF;
            const float qs = fmaf(S, dq, q0);
            const float rs = fmaf(S, dr, r0);
            const float qf = floorf(qs), rf = floorf(rs);
            const float wq = qs - qf,    wr = rs - rf;
            const int   qi = (int)qf,    ri = (int)rf;

            const float4 v = __ldg(imc + ri * PW + qi);  // (v00,v01,v10,v11)
            const float top = fmaf(wq, v.y - v.x, v.x);
            const float bot = fmaf(wq, v.w - v.z, v.z);
            acc = fmaf(wr, bot - top, acc + top);
        }
    }

    // sum the 4 kk-partials for each tt
    acc += __shfl_xor_sync(0xffffffffu, acc, 8);
    acc += __shfl_xor_sync(0xffffffffu, acc, 16);

    if (kk == 0 && t < DET)
        g_sino[(b * A_FULL + a) * DET + t] = acc;
}

// ---------------------------------------------------------------------------
// Kernel 2: data-consistency + exact ramp-filter conv, pair-packed output.
//   h[0]=0.5, h[m odd]=-2/(pi m)^2, h[m even>0]=0 (exactly the FFT filter)
// ---------------------------------------------------------------------------
__global__ void filter_kernel(const float* __restrict__ s_target)
{
    __shared__ float xcol[DET];
    __shared__ float wtab[DET];
    __shared__ float res [DET];

    const int a = blockIdx.x;
    const int b = blockIdx.y;
    const int d = threadIdx.x;

    for (int i = threadIdx.x; i < DET; i += blockDim.x) {
        float x = g_sino[(b * A_FULL + a) * DET + i];
        if ((a & 3) == 0) {
            const int j = a >> 2;
            x = __ldg(s_target + (b * DET + i) * N_ACQ + j) - x;
        }
        xcol[i] = x;

        float wm;
        if (i == 0)      wm = 0.5f;
        else if (i & 1)  { const float fm = (float)i * (float)CUDART_PI; wm = -2.0f / (fm * fm); }
        else             wm = 0.f;
        wtab[i] = wm;
    }
    __syncthreads();

    if (d < DET) {
        float acc = 0.5f * xcol[d];
        const int k0 = (d & 1) ^ 1;       // opposite parity -> |d-k| odd
        #pragma unroll 4
        for (int k = k0; k < DET; k += 2) {
            const int m = abs(d - k);
            acc += wtab[m] * xcol[k];
        }
        res[d] = acc;
    }
    __syncthreads();

    if (d < DET) {
        float2 o;
        o.x = res[d];
        o.y = (d + 1 < DET) ? res[d + 1] : 0.f;
        g_sf2[(b * A_FULL + a) * DET + d] = o;
    }
}

// ---------------------------------------------------------------------------
// Kernel 3: Filtered backprojection, chunked over angles; 1x LDG.64 / sample.
// ---------------------------------------------------------------------------
__global__ void bp_kernel(const float* __restrict__ thetas_deg)
{
    __shared__ float cs[ABP];
    __shared__ float sn[ABP];

    const int ch  = blockIdx.y;
    const int a0  = ch * ABP;
    const int na  = min(A_FULL - a0, ABP);

    if (threadIdx.x < na) {
        const float th = thetas_deg[a0 + threadIdx.x] * (float)(CUDART_PI / 180.0);
        cs[threadIdx.x] = cosf(th);
        sn[threadIdx.x] = sinf(th);
    }
    __syncthreads();

    const int p   = blockIdx.x * blockDim.x + threadIdx.x;
    const int b   = p >> 16;
    const int pix = p & 65535;
    const int y   = pix >> 8;
    const int x   = pix & 255;

    const float gx = (float)x - 127.5f;
    const float gy = (float)y - 127.5f;

    const float2* __restrict__ sfb = g_sf2 + (b * A_FULL + a0) * DET;

    float acc = 0.f;
    #pragma unroll 3
    for (int a = 0; a < na; a++) {
        const float t  = fmaf(cs[a], gx, fmaf(sn[a], gy, (float)(DET - 1) * 0.5f));
        const float t0 = floorf(t);
        const float w  = t - t0;
        const int   i  = (int)t0;           // always in [0, 360]
        const float2 v = __ldg(sfb + a * DET + i);
        acc = fmaf(w, v.y - v.x, acc + v.x);
    }
    g_bp[ch * (NB * IMG * IMG) + p] = acc;
}

// ---------------------------------------------------------------------------
// Kernel 4: reduce bp partials + scale.
// ---------------------------------------------------------------------------
__global__ void bp_reduce_kernel(float* __restrict__ out)
{
    const int p = blockIdx.x * blockDim.x + threadIdx.x;
    if (p >= NB * IMG * IMG) return;
    float acc = 0.f;
    #pragma unroll
    for (int ci = 0; ci < NCHBP; ci++)
        acc += g_bp[ci * (NB * IMG * IMG) + p];
    out[p] = acc * (float)(CUDART_PI / (2.0 * A_FULL));
}

// ---------------------------------------------------------------------------
extern "C" void kernel_launch(void* const* d_in, const int* in_sizes, int n_in,
                              void* d_out, int out_size)
{
    const float* x_source = nullptr;
    const float* s_target = nullptr;
    const float* thetas   = nullptr;
    for (int i = 0; i < n_in; i++) {
        if      (in_sizes[i] == NB * IMG * IMG)   x_source = (const float*)d_in[i];
        else if (in_sizes[i] == NB * DET * N_ACQ) s_target = (const float*)d_in[i];
        else if (in_sizes[i] == A_FULL)           thetas   = (const float*)d_in[i];
    }

    prep_kernel     <<<(NB * PH * PW + 255) / 256, 256>>>(x_source);
    radon_kernel    <<<dim3(A_FULL, NB, TTILES), TPB>>>(thetas);
    filter_kernel   <<<dim3(A_FULL, NB), 384>>>(s_target);
    bp_kernel       <<<dim3(512, NCHBP), 256>>>(thetas);
    bp_reduce_kernel<<<512, 256>>>((float*)d_out);
}

// round 8
// speedup vs baseline: 1.1048x; 1.0056x over previous
#include <cuda_runtime.h>
#include <math_constants.h>

#define IMG    256
#define DET    362          // int(256*sqrt(2)+0.5)
#define A_FULL 177          // (45-1)*4 + 1
#define N_ACQ  45
#define NB     2

// Padded image geometry: 2-cell zero border (coords reach index -2..256)
#define PW     264          // padded row stride in float4 quads
#define PH     260
#define POFF   (2 * PW + 2)

// radon warp tiling: 8 t-bins x 4 k-samples per warp
#define TPB    256          // 8 warps -> 64 t-bins per block
#define TTILES 6            // ceil(362/64)

// bp chunking
#define NCHBP  4
#define ABP    45           // ceil(177/4)

// Scratch (allocation-free)
__device__ float  g_sino[NB * A_FULL * DET];   // radon output
__device__ float2 g_sf2 [NB * A_FULL * DET];   // filtered sinogram, pair-packed
__device__ float4 g_imQ  [NB * PH * PW];       // quad-packed padded image
__device__ float4 g_imTQ [NB * PH * PW];       // quad-packed padded transposed image
__device__ float  g_bp  [NCHBP * NB * IMG * IMG];

// ---------------------------------------------------------------------------
// Kernel 0: build quad-packed padded images.
// imQ [r][c] = (I[r][c],  I[r][c+1],  I[r+1][c],  I[r+1][c+1])
// imTQ[r][c] = (I[c][r],  I[c+1][r],  I[c][r+1],  I[c+1][r+1])
// ---------------------------------------------------------------------------
__global__ void prep_kernel(const float* __restrict__ img)
{
    const int i = blockIdx.x * blockDim.x + threadIdx.x;
    if (i >= NB * PH * PW) return;
    const int b   = i / (PH * PW);
    const int rem = i - b * (PH * PW);
    const int r   = rem / PW - 2;
    const int c   = rem - (r + 2) * PW - 2;
    const float* im = img + b * IMG * IMG;

    const bool rv0 = ((unsigned)r       < IMG);
    const bool rv1 = ((unsigned)(r + 1) < IMG);
    const bool cv0 = ((unsigned)c       < IMG);
    const bool cv1 = ((unsigned)(c + 1) < IMG);

    float4 v, vt;
    v.x  = (rv0 && cv0) ? __ldg(im + r * IMG + c)             : 0.f;
    v.y  = (rv0 && cv1) ? __ldg(im + r * IMG + c + 1)         : 0.f;
    v.z  = (rv1 && cv0) ? __ldg(im + (r + 1) * IMG + c)       : 0.f;
    v.w  = (rv1 && cv1) ? __ldg(im + (r + 1) * IMG + c + 1)   : 0.f;
    vt.x = (cv0 && rv0) ? __ldg(im + c * IMG + r)             : 0.f;
    vt.y = (cv1 && rv0) ? __ldg(im + (c + 1) * IMG + r)       : 0.f;
    vt.z = (cv0 && rv1) ? __ldg(im + c * IMG + r + 1)         : 0.f;
    vt.w = (cv1 && rv1) ? __ldg(im + (c + 1) * IMG + r + 1)   : 0.f;
    g_imQ [i] = v;
    g_imTQ[i] = vt;
}

// ---------------------------------------------------------------------------
// Kernel 1: Radon transform. grid = (A_FULL, NB, TTILES), block = 256.
// Warp = 8 t-bins x 4 k-strides; one LDG.128 per bilinear sample.
// ---------------------------------------------------------------------------
__global__ void radon_kernel(const float* __restrict__ thetas_deg)
{
    const int a    = blockIdx.x;
    const int b    = blockIdx.y;
    const int w    = threadIdx.x >> 5;
    const int lane = threadIdx.x & 31;
    const int tt   = lane & 7;
    const int kk   = lane >> 3;
    const int t    = blockIdx.z * 64 + w * 8 + tt;

    const float th = thetas_deg[a] * (float)(CUDART_PI / 180.0);
    const float c  = cosf(th);
    const float s  = sinf(th);

    const bool swp = (s > fabsf(c));
    const float4* imc = (swp ? g_imTQ : g_imQ) + b * PH * PW + POFF;

    // per-lane ray parameters (valid only for t < DET)
    float q0 = 0.f, r0 = 0.f, dq = 0.f, dr = 0.f;
    int klo = DET, khi = 0;                 // empty interval by default
    if (t < DET) {
        const float T  = (float)t - (float)(DET - 1) * 0.5f;
        const float bx = T * c + 127.5f;
        const float by = T * s + 127.5f;
        if (swp) { q0 = by; r0 = bx; dq =  c; dr = -s; }
        else     { q0 = bx; r0 = by; dq = -s; dr =  c; }

        float Slo = -1e9f, Shi = 1e9f;
        if (dq > 1e-6f)       { Slo = fmaxf(Slo, (-1.f - q0) / dq); Shi = fminf(Shi, (256.f - q0) / dq); }
        else if (dq < -1e-6f) { Slo = fmaxf(Slo, (256.f - q0) / dq); Shi = fminf(Shi, (-1.f - q0) / dq); }
        else if (q0 <= -1.f || q0 >= 256.f) Shi = -2e9f;
        if (dr > 1e-6f)       { Slo = fmaxf(Slo, (-1.f - r0) / dr); Shi = fminf(Shi, (256.f - r0) / dr); }
        else if (dr < -1e-6f) { Slo = fmaxf(Slo, (256.f - r0) / dr); Shi = fminf(Shi, (-1.f - r0) / dr); }
        else if (r0 <= -1.f || r0 >= 256.f) Shi = -2e9f;

        const float HALF = (float)(DET - 1) * 0.5f;
        klo = (int)floorf(Slo + HALF);          // pad absorbs <=1-step slack
        khi = (int)ceilf (Shi + HALF) + 1;
        klo = max(klo, 0);
        khi = min(khi, DET);
        if (khi < klo) { klo = DET; khi = 0; }
    }

    // warp-uniform k range
    const int kmin = __reduce_min_sync(0xffffffffu, klo);
    const int kmax = __reduce_max_sync(0xffffffffu, khi);

    const float HALF = (float)(DET - 1) * 0.5f;
    float acc = 0.f;
    for (int k = kmin + kk; k < kmax; k += 4) {
        if (k >= klo && k < khi) {
            const float S  = (float)k - HALF;
            const float qs = fmaf(S, dq, q0);
            const float rs = fmaf(S, dr, r0);
            const float qf = floorf(qs), rf = floorf(rs);
            const float wq = qs - qf,    wr = rs - rf;
            const int   qi = (int)qf,    ri = (int)rf;

            const float4 v = __ldg(imc + ri * PW + qi);  // (v00,v01,v10,v11)
            const float top = fmaf(wq, v.y - v.x, v.x);
            const float bot = fmaf(wq, v.w - v.z, v.z);
            acc = fmaf(wr, bot - top, acc + top);
        }
    }

    // sum the 4 kk-partials for each tt
    acc += __shfl_xor_sync(0xffffffffu, acc, 8);
    acc += __shfl_xor_sync(0xffffffffu, acc, 16);

    if (kk == 0 && t < DET)
        g_sino[(b * A_FULL + a) * DET + t] = acc;
}

// ---------------------------------------------------------------------------
// Kernel 2: data-consistency + exact ramp-filter conv, pair-packed output.
//   h[0]=0.5, h[m odd]=-2/(pi m)^2, h[m even>0]=0 (exactly the FFT filter)
// ---------------------------------------------------------------------------
__global__ void filter_kernel(const float* __restrict__ s_target)
{
    __shared__ float xcol[DET];
    __shared__ float wtab[DET];
    __shared__ float res [DET];

    const int a = blockIdx.x;
    const int b = blockIdx.y;
    const int d = threadIdx.x;

    for (int i = threadIdx.x; i < DET; i += blockDim.x) {
        float x = g_sino[(b * A_FULL + a) * DET + i];
        if ((a & 3) == 0) {
            const int j = a >> 2;
            x = __ldg(s_target + (b * DET + i) * N_ACQ + j) - x;
        }
        xcol[i] = x;

        float wm;
        if (i == 0)      wm = 0.5f;
        else if (i & 1)  { const float fm = (float)i * (float)CUDART_PI; wm = -2.0f / (fm * fm); }
        else             wm = 0.f;
        wtab[i] = wm;
    }
    __syncthreads();

    if (d < DET) {
        float acc = 0.5f * xcol[d];
        const int k0 = (d & 1) ^ 1;       // opposite parity -> |d-k| odd
        #pragma unroll 4
        for (int k = k0; k < DET; k += 2) {
            const int m = abs(d - k);
            acc += wtab[m] * xcol[k];
        }
        res[d] = acc;
    }
    __syncthreads();

    if (d < DET) {
        float2 o;
        o.x = res[d];
        o.y = (d + 1 < DET) ? res[d + 1] : 0.f;
        g_sf2[(b * A_FULL + a) * DET + d] = o;
    }
}

// ---------------------------------------------------------------------------
// Kernel 3: Filtered backprojection, chunked over angles; 1x LDG.64 / sample.
// ---------------------------------------------------------------------------
__global__ void bp_kernel(const float* __restrict__ thetas_deg)
{
    __shared__ float cs[ABP];
    __shared__ float sn[ABP];

    const int ch  = blockIdx.y;
    const int a0  = ch * ABP;
    const int na  = min(A_FULL - a0, ABP);

    if (threadIdx.x < na) {
        const float th = thetas_deg[a0 + threadIdx.x] * (float)(CUDART_PI / 180.0);
        cs[threadIdx.x] = cosf(th);
        sn[threadIdx.x] = sinf(th);
    }
    __syncthreads();

    const int p   = blockIdx.x * blockDim.x + threadIdx.x;
    const int b   = p >> 16;
    const int pix = p & 65535;
    const int y   = pix >> 8;
    const int x   = pix & 255;

    const float gx = (float)x - 127.5f;
    const float gy = (float)y - 127.5f;

    const float2* __restrict__ sfb = g_sf2 + (b * A_FULL + a0) * DET;

    float acc = 0.f;
    #pragma unroll 3
    for (int a = 0; a < na; a++) {
        const float t  = fmaf(cs[a], gx, fmaf(sn[a], gy, (float)(DET - 1) * 0.5f));
        const float t0 = floorf(t);
        const float w  = t - t0;
        const int   i  = (int)t0;           // always in [0, 360]
        const float2 v = __ldg(sfb + a * DET + i);
        acc = fmaf(w, v.y - v.x, acc + v.x);
    }
    g_bp[ch * (NB * IMG * IMG) + p] = acc;
}

// ---------------------------------------------------------------------------
// Kernel 4: reduce bp partials + scale.
// ---------------------------------------------------------------------------
__global__ void bp_reduce_kernel(float* __restrict__ out)
{
    const int p = blockIdx.x * blockDim.x + threadIdx.x;
    if (p >= NB * IMG * IMG) return;
    float acc = 0.f;
    #pragma unroll
    for (int ci = 0; ci < NCHBP; ci++)
        acc += g_bp[ci * (NB * IMG * IMG) + p];
    out[p] = acc * (float)(CUDART_PI / (2.0 * A_FULL));
}

// ---------------------------------------------------------------------------
extern "C" void kernel_launch(void* const* d_in, const int* in_sizes, int n_in,
                              void* d_out, int out_size)
{
    const float* x_source = nullptr;
    const float* s_target = nullptr;
    const float* thetas   = nullptr;
    for (int i = 0; i < n_in; i++) {
        if      (in_sizes[i] == NB * IMG * IMG)   x_source = (const float*)d_in[i];
        else if (in_sizes[i] == NB * DET * N_ACQ) s_target = (const float*)d_in[i];
        else if (in_sizes[i] == A_FULL)           thetas   = (const float*)d_in[i];
    }

    prep_kernel     <<<(NB * PH * PW + 255) / 256, 256>>>(x_source);
    radon_kernel    <<<dim3(A_FULL, NB, TTILES), TPB>>>(thetas);
    filter_kernel   <<<dim3(A_FULL, NB), 384>>>(s_target);
    bp_kernel       <<<dim3(512, NCHBP), 256>>>(thetas);
    bp_reduce_kernel<<<512, 256>>>((float*)d_out);
}

// round 9
// speedup vs baseline: 1.1092x; 1.0040x over previous
#include <cuda_runtime.h>
#include <math_constants.h>

#define IMG    256
#define DET    362          // int(256*sqrt(2)+0.5)
#define A_FULL 177          // (45-1)*4 + 1
#define N_ACQ  45
#define NB     2

// Padded image geometry: 2-cell zero border (coords reach index -2..256)
#define PW     264          // padded row stride in float4 quads
#define PH     260
#define POFF   (2 * PW + 2)

// radon warp tiling: 8 t-bins x 4 k-samples per warp
#define TPB    256          // 8 warps -> 64 t-bins per block
#define TTILES 6            // ceil(362/64)

// bp chunking
#define NCHBP  4
#define ABP    45           // ceil(177/4)
#define NPAIR  (NB * IMG * IMG / 2)   // 65536 pixel pairs

// Scratch (allocation-free)
__device__ float  g_sino[NB * A_FULL * DET];   // radon output
__device__ float2 g_sf2 [NB * A_FULL * DET];   // filtered sinogram, pair-packed
__device__ float4 g_imQ  [NB * PH * PW];       // quad-packed padded image
__device__ float4 g_imTQ [NB * PH * PW];       // quad-packed padded transposed image
__device__ float2 g_bp2 [NCHBP * NPAIR];       // bp partials, pixel-pair packed

// ---------------------------------------------------------------------------
// Kernel 0: build quad-packed padded images.
// imQ [r][c] = (I[r][c],  I[r][c+1],  I[r+1][c],  I[r+1][c+1])
// imTQ[r][c] = (I[c][r],  I[c+1][r],  I[c][r+1],  I[c+1][r+1])
// ---------------------------------------------------------------------------
__global__ void prep_kernel(const float* __restrict__ img)
{
    const int i = blockIdx.x * blockDim.x + threadIdx.x;
    if (i >= NB * PH * PW) return;
    const int b   = i / (PH * PW);
    const int rem = i - b * (PH * PW);
    const int r   = rem / PW - 2;
    const int c   = rem - (r + 2) * PW - 2;
    const float* im = img + b * IMG * IMG;

    const bool rv0 = ((unsigned)r       < IMG);
    const bool rv1 = ((unsigned)(r + 1) < IMG);
    const bool cv0 = ((unsigned)c       < IMG);
    const bool cv1 = ((unsigned)(c + 1) < IMG);

    float4 v, vt;
    v.x  = (rv0 && cv0) ? __ldg(im + r * IMG + c)             : 0.f;
    v.y  = (rv0 && cv1) ? __ldg(im + r * IMG + c + 1)         : 0.f;
    v.z  = (rv1 && cv0) ? __ldg(im + (r + 1) * IMG + c)       : 0.f;
    v.w  = (rv1 && cv1) ? __ldg(im + (r + 1) * IMG + c + 1)   : 0.f;
    vt.x = (cv0 && rv0) ? __ldg(im + c * IMG + r)             : 0.f;
    vt.y = (cv1 && rv0) ? __ldg(im + (c + 1) * IMG + r)       : 0.f;
    vt.z = (cv0 && rv1) ? __ldg(im + c * IMG + r + 1)         : 0.f;
    vt.w = (cv1 && rv1) ? __ldg(im + (c + 1) * IMG + r + 1)   : 0.f;
    g_imQ [i] = v;
    g_imTQ[i] = vt;
}

// ---------------------------------------------------------------------------
// Kernel 1: Radon transform. grid = (A_FULL, NB, TTILES), block = 256.
// Warp = 8 t-bins x 4 k-strides; one LDG.128 per bilinear sample.
// ---------------------------------------------------------------------------
__global__ void radon_kernel(const float* __restrict__ thetas_deg)
{
    const int a    = blockIdx.x;
    const int b    = blockIdx.y;
    const int w    = threadIdx.x >> 5;
    const int lane = threadIdx.x & 31;
    const int tt   = lane & 7;
    const int kk   = lane >> 3;
    const int t    = blockIdx.z * 64 + w * 8 + tt;

    const float th = thetas_deg[a] * (float)(CUDART_PI / 180.0);
    const float c  = cosf(th);
    const float s  = sinf(th);

    const bool swp = (s > fabsf(c));
    const float4* imc = (swp ? g_imTQ : g_imQ) + b * PH * PW + POFF;

    float q0 = 0.f, r0 = 0.f, dq = 0.f, dr = 0.f;
    int klo = DET, khi = 0;
    if (t < DET) {
        const float T  = (float)t - (float)(DET - 1) * 0.5f;
        const float bx = T * c + 127.5f;
        const float by = T * s + 127.5f;
        if (swp) { q0 = by; r0 = bx; dq =  c; dr = -s; }
        else     { q0 = bx; r0 = by; dq = -s; dr =  c; }

        float Slo = -1e9f, Shi = 1e9f;
        if (dq > 1e-6f)       { Slo = fmaxf(Slo, (-1.f - q0) / dq); Shi = fminf(Shi, (256.f - q0) / dq); }
        else if (dq < -1e-6f) { Slo = fmaxf(Slo, (256.f - q0) / dq); Shi = fminf(Shi, (-1.f - q0) / dq); }
        else if (q0 <= -1.f || q0 >= 256.f) Shi = -2e9f;
        if (dr > 1e-6f)       { Slo = fmaxf(Slo, (-1.f - r0) / dr); Shi = fminf(Shi, (256.f - r0) / dr); }
        else if (dr < -1e-6f) { Slo = fmaxf(Slo, (256.f - r0) / dr); Shi = fminf(Shi, (-1.f - r0) / dr); }
        else if (r0 <= -1.f || r0 >= 256.f) Shi = -2e9f;

        const float HALF = (float)(DET - 1) * 0.5f;
        klo = (int)floorf(Slo + HALF);
        khi = (int)ceilf (Shi + HALF) + 1;
        klo = max(klo, 0);
        khi = min(khi, DET);
        if (khi < klo) { klo = DET; khi = 0; }
    }

    const int kmin = __reduce_min_sync(0xffffffffu, klo);
    const int kmax = __reduce_max_sync(0xffffffffu, khi);

    const float HALF = (float)(DET - 1) * 0.5f;
    float acc = 0.f;
    for (int k = kmin + kk; k < kmax; k += 4) {
        if (k >= klo && k < khi) {
            const float S  = (float)k - HALF;
            const float qs = fmaf(S, dq, q0);
            const float rs = fmaf(S, dr, r0);
            const float qf = floorf(qs), rf = floorf(rs);
            const float wq = qs - qf,    wr = rs - rf;
            const int   qi = (int)qf,    ri = (int)rf;

            const float4 v = __ldg(imc + ri * PW + qi);  // (v00,v01,v10,v11)
            const float top = fmaf(wq, v.y - v.x, v.x);
            const float bot = fmaf(wq, v.w - v.z, v.z);
            acc = fmaf(wr, bot - top, acc + top);
        }
    }

    acc += __shfl_xor_sync(0xffffffffu, acc, 8);
    acc += __shfl_xor_sync(0xffffffffu, acc, 16);

    if (kk == 0 && t < DET)
        g_sino[(b * A_FULL + a) * DET + t] = acc;
}

// ---------------------------------------------------------------------------
// Kernel 2: data-consistency + exact ramp-filter conv, pair-packed output.
//   h[0]=0.5, h[m odd]=-2/(pi m)^2, h[m even>0]=0 (exactly the FFT filter)
// ---------------------------------------------------------------------------
__global__ void filter_kernel(const float* __restrict__ s_target)
{
    __shared__ float xcol[DET];
    __shared__ float wtab[DET];
    __shared__ float res [DET];

    const int a = blockIdx.x;
    const int b = blockIdx.y;
    const int d = threadIdx.x;

    for (int i = threadIdx.x; i < DET; i += blockDim.x) {
        float x = g_sino[(b * A_FULL + a) * DET + i];
        if ((a & 3) == 0) {
            const int j = a >> 2;
            x = __ldg(s_target + (b * DET + i) * N_ACQ + j) - x;
        }
        xcol[i] = x;

        float wm;
        if (i == 0)      wm = 0.5f;
        else if (i & 1)  { const float fm = (float)i * (float)CUDART_PI; wm = -2.0f / (fm * fm); }
        else             wm = 0.f;
        wtab[i] = wm;
    }
    __syncthreads();

    if (d < DET) {
        float acc = 0.5f * xcol[d];
        const int k0 = (d & 1) ^ 1;       // opposite parity -> |d-k| odd
        #pragma unroll 4
        for (int k = k0; k < DET; k += 2) {
            const int m = abs(d - k);
            acc += wtab[m] * xcol[k];
        }
        res[d] = acc;
    }
    __syncthreads();

    if (d < DET) {
        float2 o;
        o.x = res[d];
        o.y = (d + 1 < DET) ? res[d + 1] : 0.f;
        g_sf2[(b * A_FULL + a) * DET + d] = o;
    }
}

// ---------------------------------------------------------------------------
// Kernel 3: Filtered backprojection. 2 adjacent x-pixels per thread,
// two independent load->lerp chains (MLP=2), truncation instead of floorf.
// grid = (256, NCHBP), block = 256.
// ---------------------------------------------------------------------------
__global__ void bp_kernel(const float* __restrict__ thetas_deg)
{
    __shared__ float cs[ABP];
    __shared__ float sn[ABP];

    const int ch  = blockIdx.y;
    const int a0  = ch * ABP;
    const int na  = min(A_FULL - a0, ABP);

    if (threadIdx.x < na) {
        const float th = thetas_deg[a0 + threadIdx.x] * (float)(CUDART_PI / 180.0);
        cs[threadIdx.x] = cosf(th);
        sn[threadIdx.x] = sinf(th);
    }
    __syncthreads();

    const int p    = blockIdx.x * blockDim.x + threadIdx.x;  // 0..65535 pair id
    const int b    = p >> 15;
    const int pix  = (p & 32767) << 1;                       // even pixel
    const int y    = pix >> 8;
    const int x    = pix & 255;

    const float gy  = (float)y - 127.5f;
    const float gx0 = (float)x - 127.5f;
    const float gx1 = gx0 + 1.0f;

    const float2* __restrict__ sfb = g_sf2 + (b * A_FULL + a0) * DET;

    float acc0 = 0.f, acc1 = 0.f;
    #pragma unroll 5
    for (int a = 0; a < na; a++) {
        const float base = fmaf(sn[a], gy, (float)(DET - 1) * 0.5f);
        const float t0f  = fmaf(cs[a], gx0, base);       // always > 0
        const float t1f  = fmaf(cs[a], gx1, base);
        const int   i0   = (int)t0f;                     // trunc == floor (t>0)
        const int   i1   = (int)t1f;
        const float w0   = t0f - (float)i0;
        const float w1   = t1f - (float)i1;
        const float2 v0  = __ldg(sfb + a * DET + i0);
        const float2 v1  = __ldg(sfb + a * DET + i1);
        acc0 = fmaf(w0, v0.y - v0.x, acc0 + v0.x);
        acc1 = fmaf(w1, v1.y - v1.x, acc1 + v1.x);
    }
    float2 o; o.x = acc0; o.y = acc1;
    g_bp2[ch * NPAIR + p] = o;
}

// ---------------------------------------------------------------------------
// Kernel 4: reduce bp partials + scale (pair-packed).
// ---------------------------------------------------------------------------
__global__ void bp_reduce_kernel(float2* __restrict__ out)
{
    const int p = blockIdx.x * blockDim.x + threadIdx.x;
    if (p >= NPAIR) return;
    float ax = 0.f, ay = 0.f;
    #pragma unroll
    for (int ci = 0; ci < NCHBP; ci++) {
        const float2 v = g_bp2[ci * NPAIR + p];
        ax += v.x; ay += v.y;
    }
    const float sc = (float)(CUDART_PI / (2.0 * A_FULL));
    float2 o; o.x = ax * sc; o.y = ay * sc;
    out[p] = o;
}

// ---------------------------------------------------------------------------
extern "C" void kernel_launch(void* const* d_in, const int* in_sizes, int n_in,
                              void* d_out, int out_size)
{
    const float* x_source = nullptr;
    const float* s_target = nullptr;
    const float* thetas   = nullptr;
    for (int i = 0; i < n_in; i++) {
        if      (in_sizes[i] == NB * IMG * IMG)   x_source = (const float*)d_in[i];
        else if (in_sizes[i] == NB * DET * N_ACQ) s_target = (const float*)d_in[i];
        else if (in_sizes[i] == A_FULL)           thetas   = (const float*)d_in[i];
    }

    prep_kernel     <<<(NB * PH * PW + 255) / 256, 256>>>(x_source);
    radon_kernel    <<<dim3(A_FULL, NB, TTILES), TPB>>>(thetas);
    filter_kernel   <<<dim3(A_FULL, NB), 384>>>(s_target);
    bp_kernel       <<<dim3(256, NCHBP), 256>>>(thetas);
    bp_reduce_kernel<<<256, 256>>>((float2*)d_out);
}